// round 2
// baseline (speedup 1.0000x reference)
#include <cuda_runtime.h>

// S4D diagonal SSM: out[h,l] = 2*Re( sum_n cmod[h,n] * z[h,n]^l ),  z = exp(w*dt)
// Factor l = 32k + j (k in [0,64), j in [0,32)):
//   out[h,32k+j] = sum_n ( Bre[n,k]*Are[n,j] - Bim[n,k]*Aim[n,j] )
// B pre-splatted in smem as (br,br,-bi,-bi); A kept natural so {a_j,a_j+1}
// register pairs feed fma.rn.f32x2 (packed fp32 FMA, sm_100+).

#define HDIM 1024
#define NDIM 64
#define LLEN 2048

#define AST   36                 // A row stride in floats (mult of 4 for LDS.128)
#define BROW  65                 // Bs row stride in float4 (odd -> conflict-free kq lanes)
#define BS_F4   (64*BROW)        // 4160 float4
#define A_FLOATS (64*AST)        // 2304 floats (per re/im table)
#define HEAD_FLOATS (BS_F4*4 + 2*A_FLOATS)   // 21248 floats = 84992 B per head
#define SMEM_FLOATS (2*HEAD_FLOATS)          // 2 heads per block: 169984 B

struct c2 { float re, im; };
__device__ __forceinline__ c2 cmul(c2 a, c2 b) {
    return { fmaf(a.re, b.re, -a.im*b.im), fmaf(a.re, b.im, a.im*b.re) };
}

__device__ __forceinline__ void fma2(unsigned long long& d,
                                     unsigned long long a,
                                     unsigned long long b) {
    asm("fma.rn.f32x2 %0, %1, %2, %0;" : "+l"(d) : "l"(a), "l"(b));
}

union U2 { unsigned long long u; float2 f; };

__global__ __launch_bounds__(256) void ssk_diag_kernel(
    const float* __restrict__ log_dt,
    const float* __restrict__ log_w_real,
    const float* __restrict__ w_imag,
    const float* __restrict__ C_re,
    const float* __restrict__ C_im,
    float* __restrict__ out)
{
    extern __shared__ float sm[];
    const int tid = threadIdx.x;

    // ---------------- Phase 1: build tables. tid = h2*128 + seg*64 + n ----------------
    {
        const int h2  = tid >> 7;
        const int seg = (tid >> 6) & 1;
        const int n   = tid & 63;
        const int h   = blockIdx.x * 2 + h2;

        float*  base = sm + h2 * HEAD_FLOATS;
        float4* Bs   = reinterpret_cast<float4*>(base);   // [64 k][BROW]
        float*  sAre = base + BS_F4 * 4;
        float*  sAim = sAre + A_FLOATS;

        const float dtv = expf(log_dt[h]);
        const float wre = -expf(log_w_real[h*NDIM + n]);
        const float wim = w_imag[h*NDIM + n];
        const float are = wre * dtv;
        const float aim = wim * dtv;

        const float er = expf(are);
        float s, c; sincosf(aim, &s, &c);
        const c2 z = { er*c, er*s };

        // cmod = 2 * C * (z - 1) / w   (fold the output factor of 2)
        const float nre = z.re - 1.0f, nim = z.im;
        const float inv = 1.0f / (wre*wre + wim*wim);
        const float tre = (nre*wre + nim*wim) * inv;
        const float tim = (nim*wre - nre*wim) * inv;
        const float cr = C_re[h*NDIM + n], ci = C_im[h*NDIM + n];
        c2 cm = { 2.0f*(cr*tre - ci*tim), 2.0f*(cr*tim + ci*tre) };

        // power ladder
        const c2 z2    = cmul(z,    z);
        const c2 z4    = cmul(z2,   z2);
        const c2 z8    = cmul(z4,   z4);
        const c2 z16   = cmul(z8,   z8);
        const c2 z32   = cmul(z16,  z16);
        const c2 z64   = cmul(z32,  z32);
        const c2 z128  = cmul(z64,  z64);
        const c2 z256  = cmul(z128, z128);
        const c2 z512  = cmul(z256, z256);
        const c2 z1024 = cmul(z512, z512);

        // A[n][j], j = 16*seg .. 16*seg+15
        c2 a = seg ? z16 : c2{1.0f, 0.0f};
        #pragma unroll
        for (int jj = 0; jj < 16; jj++) {
            sAre[n*AST + 16*seg + jj] = a.re;
            sAim[n*AST + 16*seg + jj] = a.im;
            a = cmul(a, z);
        }

        // Bs[k][n] = splat(cmod * z32^k), k = 32*seg .. 32*seg+31
        c2 b = seg ? cmul(cm, z1024) : cm;
        #pragma unroll
        for (int kk = 0; kk < 32; kk++) {
            const int k = 32*seg + kk;
            Bs[k*BROW + n] = make_float4(b.re, b.re, -b.im, -b.im);
            b = cmul(b, z32);
        }
    }
    __syncthreads();

    // ---------------- Phase 2: contraction. tid = h2*128 + kq*8 + jp ------------------
    // Thread tile: k = kq + 16*kk (kk 0..3), j = 4*jp + jj (jj 0..3)
    const int h2 = tid >> 7;
    const int t  = tid & 127;
    const int kq = t >> 3;     // 0..15
    const int jp = t & 7;      // 0..7
    const int h  = blockIdx.x * 2 + h2;

    const float* base = sm + h2 * HEAD_FLOATS;
    const char*  BsB  = reinterpret_cast<const char*>(base) + kq * (BROW*16);
    const float* sAre = base + BS_F4 * 4 + 4*jp;
    const float* sAim = sAre + A_FLOATS;

    unsigned long long acc[4][2];
    #pragma unroll
    for (int i = 0; i < 4; i++) { acc[i][0] = 0ull; acc[i][1] = 0ull; }

    #pragma unroll 8
    for (int n = 0; n < NDIM; n++) {
        // A pairs: {a_j0,a_j0+1}, {a_j0+2,a_j0+3}
        const ulonglong2 ar = *reinterpret_cast<const ulonglong2*>(sAre + n*AST);
        const ulonglong2 ai = *reinterpret_cast<const ulonglong2*>(sAim + n*AST);

        #pragma unroll
        for (int kk = 0; kk < 4; kk++) {
            // row k = kq + 16*kk ; element n
            const ulonglong2 b = *reinterpret_cast<const ulonglong2*>(
                BsB + (size_t)kk * (16*BROW*16) + (size_t)n * 16);
            // b.x = {br,br}, b.y = {-bi,-bi}
            fma2(acc[kk][0], b.x, ar.x);
            fma2(acc[kk][0], b.y, ai.x);
            fma2(acc[kk][1], b.x, ar.y);
            fma2(acc[kk][1], b.y, ai.y);
        }
    }

    // Store: l = 32*(kq+16*kk) + 4*jp + jj  -> contiguous float4, fully coalesced
    float* po = out + h*LLEN + kq*32 + jp*4;
    #pragma unroll
    for (int kk = 0; kk < 4; kk++) {
        U2 lo, hi; lo.u = acc[kk][0]; hi.u = acc[kk][1];
        *reinterpret_cast<float4*>(po + kk*512) =
            make_float4(lo.f.x, lo.f.y, hi.f.x, hi.f.y);
    }
}

extern "C" void kernel_launch(void* const* d_in, const int* in_sizes, int n_in,
                              void* d_out, int out_size)
{
    const float* log_dt     = (const float*)d_in[0];
    const float* log_w_real = (const float*)d_in[1];
    const float* w_imag     = (const float*)d_in[2];
    const float* C_re       = (const float*)d_in[3];
    const float* C_im       = (const float*)d_in[4];
    float* out = (float*)d_out;

    const int smem_bytes = SMEM_FLOATS * (int)sizeof(float);  // 169984 B
    cudaFuncSetAttribute(ssk_diag_kernel,
                         cudaFuncAttributeMaxDynamicSharedMemorySize, smem_bytes);

    ssk_diag_kernel<<<HDIM/2, 256, smem_bytes>>>(log_dt, log_w_real, w_imag,
                                                 C_re, C_im, out);
}

// round 3
// speedup vs baseline: 1.0574x; 1.0574x over previous
#include <cuda_runtime.h>

// S4D diagonal SSM: out[h,l] = 2*Re( sum_n cmod[h,n] * z[h,n]^l ),  z = exp(w*dt)
// Factor l = 64k + j (k in [0,32), j in [0,64)):
//   out[h,64k+j] = sum_n ( Bre[n,k]*Are[n,j] - Bim[n,k]*Aim[n,j] )
// B[k] = cmod * (z^64)^k pre-splatted in smem as float4 (br,br,-bi,-bi);
// A[j] = z^j natural so {a_j,a_j+1} LDS.128 pairs feed fma.rn.f32x2.

#define HDIM 1024
#define NDIM 64
#define LLEN 2048

#define AST   68                    // A row stride (floats): 64 + 4 pad
#define BROW  65                    // B row stride (float4): 64 + 1 pad
#define B_FLOATS (32*BROW*4)        // 8320 floats
#define A_FLOATS (64*AST)           // 4352 floats per plane
#define SMEM_FLOATS (B_FLOATS + 2*A_FLOATS)   // 17024 floats = 68096 B

struct c2 { float re, im; };
__device__ __forceinline__ c2 cmul(c2 a, c2 b) {
    return { fmaf(a.re, b.re, -a.im*b.im), fmaf(a.re, b.im, a.im*b.re) };
}

__device__ __forceinline__ void fma2(unsigned long long& d,
                                     unsigned long long a,
                                     unsigned long long b) {
    asm("fma.rn.f32x2 %0, %1, %2, %0;" : "+l"(d) : "l"(a), "l"(b));
}

union U2 { unsigned long long u; float2 f; };

__global__ __launch_bounds__(128) void ssk_diag_kernel(
    const float* __restrict__ log_dt,
    const float* __restrict__ log_w_real,
    const float* __restrict__ w_imag,
    const float* __restrict__ C_re,
    const float* __restrict__ C_im,
    float* __restrict__ out)
{
    extern __shared__ float sm[];
    float4* Bs  = reinterpret_cast<float4*>(sm);    // [32 k][BROW]
    float* sAre = sm + B_FLOATS;                    // [64 n][AST]
    float* sAim = sAre + A_FLOATS;

    const int h   = blockIdx.x;
    const int tid = threadIdx.x;

    // ------------- Phase 1: tables. tid = half*64 + n (2 threads per n) -------------
    {
        const int n    = tid & 63;
        const int half = tid >> 6;

        const float dtv = expf(log_dt[h]);
        const float wre = -expf(log_w_real[h*NDIM + n]);
        const float wim = w_imag[h*NDIM + n];
        const float are = wre * dtv;
        const float aim = wim * dtv;

        const float er = expf(are);
        float s, c; sincosf(aim, &s, &c);
        const c2 z = { er*c, er*s };

        // cmod = 2 * C * (z - 1) / w
        const float nre = z.re - 1.0f, nim = z.im;
        const float inv = 1.0f / (wre*wre + wim*wim);
        const float tre = (nre*wre + nim*wim) * inv;
        const float tim = (nim*wre - nre*wim) * inv;
        const float cr = C_re[h*NDIM + n], ci = C_im[h*NDIM + n];
        const c2 cm = { 2.0f*(cr*tre - ci*tim), 2.0f*(cr*tim + ci*tre) };

        // power ladder by squaring
        const c2 z2    = cmul(z,    z);
        const c2 z4    = cmul(z2,   z2);
        const c2 z8    = cmul(z4,   z4);
        const c2 z16   = cmul(z8,   z8);
        const c2 z32   = cmul(z16,  z16);
        const c2 z64   = cmul(z32,  z32);
        const c2 z128  = cmul(z64,  z64);
        const c2 z256  = cmul(z128, z128);
        const c2 z512  = cmul(z256, z256);
        const c2 z1024 = cmul(z512, z512);

        // A[n][j] = z^j, j = 32*half .. 32*half+31
        c2 a = half ? z32 : c2{1.0f, 0.0f};
        #pragma unroll
        for (int jj = 0; jj < 32; jj++) {
            sAre[n*AST + 32*half + jj] = a.re;
            sAim[n*AST + 32*half + jj] = a.im;
            a = cmul(a, z);
        }

        // Bs[k][n] = splat(cmod * z64^k), k = 16*half .. 16*half+15
        c2 b = half ? cmul(cm, z1024) : cm;
        #pragma unroll
        for (int kk = 0; kk < 16; kk++) {
            Bs[(16*half + kk)*BROW + n] = make_float4(b.re, b.re, -b.im, -b.im);
            b = cmul(b, z64);
        }
    }
    __syncthreads();

    // ------------- Phase 2: contraction. tid = jh*64 + kq*8 + jp --------------------
    // Thread tile: k = kq + 8*kk (kk 0..3), j = 32*jh + 4*jp + jj (jj 0..3)
    const int jh = tid >> 6;
    const int r  = tid & 63;
    const int kq = r >> 3;          // 0..7
    const int jp = r & 7;           // 0..7
    const int j0 = 32*jh + 4*jp;

    const char*  BsB  = reinterpret_cast<const char*>(Bs) + (size_t)kq * (BROW*16);
    const float* pAre = sAre + j0;
    const float* pAim = sAim + j0;

    unsigned long long acc[4][2];
    #pragma unroll
    for (int i = 0; i < 4; i++) { acc[i][0] = 0ull; acc[i][1] = 0ull; }

    #pragma unroll 8
    for (int n = 0; n < NDIM; n++) {
        const ulonglong2 ar = *reinterpret_cast<const ulonglong2*>(pAre + n*AST);
        const ulonglong2 ai = *reinterpret_cast<const ulonglong2*>(pAim + n*AST);

        #pragma unroll
        for (int kk = 0; kk < 4; kk++) {
            const ulonglong2 b = *reinterpret_cast<const ulonglong2*>(
                BsB + (size_t)kk * (8*BROW*16) + (size_t)n * 16);
            // b.x = {br,br}, b.y = {-bi,-bi}
            fma2(acc[kk][0], b.x, ar.x);
            fma2(acc[kk][0], b.y, ai.x);
            fma2(acc[kk][1], b.x, ar.y);
            fma2(acc[kk][1], b.y, ai.y);
        }
    }

    // Store: l = 64*(kq+8*kk) + j0 + jj -> float4, warp covers 4x(128B x interleave)
    float* po = out + h*LLEN + kq*64 + j0;
    #pragma unroll
    for (int kk = 0; kk < 4; kk++) {
        U2 lo, hi; lo.u = acc[kk][0]; hi.u = acc[kk][1];
        *reinterpret_cast<float4*>(po + kk*512) =
            make_float4(lo.f.x, lo.f.y, hi.f.x, hi.f.y);
    }
}

extern "C" void kernel_launch(void* const* d_in, const int* in_sizes, int n_in,
                              void* d_out, int out_size)
{
    const float* log_dt     = (const float*)d_in[0];
    const float* log_w_real = (const float*)d_in[1];
    const float* w_imag     = (const float*)d_in[2];
    const float* C_re       = (const float*)d_in[3];
    const float* C_im       = (const float*)d_in[4];
    float* out = (float*)d_out;

    const int smem_bytes = SMEM_FLOATS * (int)sizeof(float);   // 68096 B
    cudaFuncSetAttribute(ssk_diag_kernel,
                         cudaFuncAttributeMaxDynamicSharedMemorySize, smem_bytes);

    ssk_diag_kernel<<<HDIM, 128, smem_bytes>>>(log_dt, log_w_real, w_imag,
                                               C_re, C_im, out);
}

// round 4
// speedup vs baseline: 1.3383x; 1.2656x over previous
#include <cuda_runtime.h>

// S4D diagonal SSM: out[h,l] = 2*Re( sum_n cmod[h,n] * z[h,n]^l ),  z = exp(w*dt)
// Factor l = 64k + j (k in [0,32), j in [0,64)):
//   out[h,64k+j] = sum_n ( Bre[n,k]*Are[n,j] - Bim[n,k]*Aim[n,j] )
// Packing trick: A[n][j]=(ar,ai) float2, B[k][n]=(br,-bi) float2.
// fma.rn.f32x2 acc += B ⊗ A accumulates {Σ br*ar, Σ -bi*ai}; out = lo+hi.
// No splats, half the smem of the splat scheme, natural float2 loads.

#define HDIM 1024
#define NDIM 64
#define LLEN 2048

#define AST 66                       // A row stride in float2 (64 + 2 pad; 16B-aligned)
#define BST 66                       // B row stride in float2
#define A_FLOATS (64*AST*2)          // 8448 floats (33792 B)
#define B_FLOATS (32*BST*2)          // 4224 floats (16896 B)
#define SMEM_FLOATS (A_FLOATS + B_FLOATS)   // 12672 floats = 50688 B

struct c2 { float re, im; };
__device__ __forceinline__ c2 cmul(c2 a, c2 b) {
    return { fmaf(a.re, b.re, -a.im*b.im), fmaf(a.re, b.im, a.im*b.re) };
}

__device__ __forceinline__ void fma2(unsigned long long& d,
                                     unsigned long long a,
                                     unsigned long long b) {
    asm("fma.rn.f32x2 %0, %1, %2, %0;" : "+l"(d) : "l"(a), "l"(b));
}

union U2 { unsigned long long u; float2 f; };

__global__ __launch_bounds__(128, 4) void ssk_diag_kernel(
    const float* __restrict__ log_dt,
    const float* __restrict__ log_w_real,
    const float* __restrict__ w_imag,
    const float* __restrict__ C_re,
    const float* __restrict__ C_im,
    float* __restrict__ out)
{
    extern __shared__ float sm[];
    float2* sA = reinterpret_cast<float2*>(sm);              // [64 n][AST]
    float2* sB = reinterpret_cast<float2*>(sm + A_FLOATS);   // [32 k][BST]

    const int h   = blockIdx.x;
    const int tid = threadIdx.x;

    // ------------- Phase 1: tables. tid = half*64 + n (2 threads per n) -------------
    {
        const int n    = tid & 63;
        const int half = tid >> 6;

        const float dtv = expf(log_dt[h]);
        const float wre = -expf(log_w_real[h*NDIM + n]);
        const float wim = w_imag[h*NDIM + n];
        const float are = wre * dtv;
        const float aim = wim * dtv;

        const float er = expf(are);
        float s, c; sincosf(aim, &s, &c);
        const c2 z = { er*c, er*s };

        // cmod = 2 * C * (z - 1) / w  (fold output factor 2)
        const float nre = z.re - 1.0f, nim = z.im;
        const float inv = 1.0f / (wre*wre + wim*wim);
        const float tre = (nre*wre + nim*wim) * inv;
        const float tim = (nim*wre - nre*wim) * inv;
        const float cr = C_re[h*NDIM + n], ci = C_im[h*NDIM + n];
        const c2 cm = { 2.0f*(cr*tre - ci*tim), 2.0f*(cr*tim + ci*tre) };

        // power ladder by squaring
        const c2 z2    = cmul(z,    z);
        const c2 z4    = cmul(z2,   z2);
        const c2 z8    = cmul(z4,   z4);
        const c2 z16   = cmul(z8,   z8);
        const c2 z32   = cmul(z16,  z16);
        const c2 z64   = cmul(z32,  z32);
        const c2 z128  = cmul(z64,  z64);
        const c2 z256  = cmul(z128, z128);
        const c2 z512  = cmul(z256, z256);
        const c2 z1024 = cmul(z512, z512);

        // A[n][j] = (re,im) of z^j, j = 32*half .. 32*half+31
        c2 a = half ? z32 : c2{1.0f, 0.0f};
        #pragma unroll
        for (int jj = 0; jj < 32; jj++) {
            sA[n*AST + 32*half + jj] = make_float2(a.re, a.im);
            a = cmul(a, z);
        }

        // B[k][n] = (re, -im) of cmod * z64^k, k = 16*half .. 16*half+15
        c2 b = half ? cmul(cm, z1024) : cm;
        #pragma unroll
        for (int kk = 0; kk < 16; kk++) {
            sB[(16*half + kk)*BST + n] = make_float2(b.re, -b.im);
            b = cmul(b, z64);
        }
    }
    __syncthreads();

    // ------------- Phase 2: contraction. tid = jp*8 + kq ----------------------------
    // Thread tile: k = kq + 8*kk (kk 0..3), j = 4*jp + jj (jj 0..3). 16 outputs.
    const int jp = tid >> 3;    // 0..15
    const int kq = tid & 7;     // 0..7

    const char* pA = reinterpret_cast<const char*>(sA) + (size_t)jp * 32;
    const char* pB = reinterpret_cast<const char*>(sB) + (size_t)kq * (BST*8);

    unsigned long long acc[4][4];   // [kk][jj]
    #pragma unroll
    for (int i = 0; i < 4; i++)
        #pragma unroll
        for (int jj = 0; jj < 4; jj++) acc[i][jj] = 0ull;

    // Double-buffered over n-pairs (32 steps). B LDS.128 fetches (n, n+1) per row.
    #define LDA(off) (*reinterpret_cast<const ulonglong2*>(pA + (off)))
    #define LDB(off) (*reinterpret_cast<const ulonglong2*>(pB + (off)))

    ulonglong2 a0 = LDA(0),        a1 = LDA(16);         // n=0: j pairs
    ulonglong2 a2 = LDA(AST*8),    a3 = LDA(AST*8 + 16); // n=1
    ulonglong2 b0 = LDB(0);
    ulonglong2 b1 = LDB(BST*8*8);
    ulonglong2 b2 = LDB(BST*8*16);
    ulonglong2 b3 = LDB(BST*8*24);

    #pragma unroll 4
    for (int n2 = 0; n2 < 32; n2++) {
        const ulonglong2 ca0 = a0, ca1 = a1, ca2 = a2, ca3 = a3;
        const ulonglong2 cb0 = b0, cb1 = b1, cb2 = b2, cb3 = b3;

        if (n2 < 31) {
            const size_t nb = (size_t)(2*n2 + 2);
            a0 = LDA(nb*AST*8);        a1 = LDA(nb*AST*8 + 16);
            a2 = LDA((nb+1)*AST*8);    a3 = LDA((nb+1)*AST*8 + 16);
            b0 = LDB(nb*8);
            b1 = LDB(BST*8*8  + nb*8);
            b2 = LDB(BST*8*16 + nb*8);
            b3 = LDB(BST*8*24 + nb*8);
        }

        // even n: b*.x ; odd n: b*.y
        fma2(acc[0][0], cb0.x, ca0.x);  fma2(acc[0][1], cb0.x, ca0.y);
        fma2(acc[0][2], cb0.x, ca1.x);  fma2(acc[0][3], cb0.x, ca1.y);
        fma2(acc[1][0], cb1.x, ca0.x);  fma2(acc[1][1], cb1.x, ca0.y);
        fma2(acc[1][2], cb1.x, ca1.x);  fma2(acc[1][3], cb1.x, ca1.y);
        fma2(acc[2][0], cb2.x, ca0.x);  fma2(acc[2][1], cb2.x, ca0.y);
        fma2(acc[2][2], cb2.x, ca1.x);  fma2(acc[2][3], cb2.x, ca1.y);
        fma2(acc[3][0], cb3.x, ca0.x);  fma2(acc[3][1], cb3.x, ca0.y);
        fma2(acc[3][2], cb3.x, ca1.x);  fma2(acc[3][3], cb3.x, ca1.y);

        fma2(acc[0][0], cb0.y, ca2.x);  fma2(acc[0][1], cb0.y, ca2.y);
        fma2(acc[0][2], cb0.y, ca3.x);  fma2(acc[0][3], cb0.y, ca3.y);
        fma2(acc[1][0], cb1.y, ca2.x);  fma2(acc[1][1], cb1.y, ca2.y);
        fma2(acc[1][2], cb1.y, ca3.x);  fma2(acc[1][3], cb1.y, ca3.y);
        fma2(acc[2][0], cb2.y, ca2.x);  fma2(acc[2][1], cb2.y, ca2.y);
        fma2(acc[2][2], cb2.y, ca3.x);  fma2(acc[2][3], cb2.y, ca3.y);
        fma2(acc[3][0], cb3.y, ca2.x);  fma2(acc[3][1], cb3.y, ca2.y);
        fma2(acc[3][2], cb3.y, ca3.x);  fma2(acc[3][3], cb3.y, ca3.y);
    }
    #undef LDA
    #undef LDB

    // Reduce packed halves and store: l = 64*(kq+8*kk) + 4*jp + jj
    float* po = out + h*LLEN + kq*64 + jp*4;
    #pragma unroll
    for (int kk = 0; kk < 4; kk++) {
        float4 v;
        { U2 u; u.u = acc[kk][0]; v.x = u.f.x + u.f.y; }
        { U2 u; u.u = acc[kk][1]; v.y = u.f.x + u.f.y; }
        { U2 u; u.u = acc[kk][2]; v.z = u.f.x + u.f.y; }
        { U2 u; u.u = acc[kk][3]; v.w = u.f.x + u.f.y; }
        *reinterpret_cast<float4*>(po + kk*512) = v;
    }
}

extern "C" void kernel_launch(void* const* d_in, const int* in_sizes, int n_in,
                              void* d_out, int out_size)
{
    const float* log_dt     = (const float*)d_in[0];
    const float* log_w_real = (const float*)d_in[1];
    const float* w_imag     = (const float*)d_in[2];
    const float* C_re       = (const float*)d_in[3];
    const float* C_im       = (const float*)d_in[4];
    float* out = (float*)d_out;

    const int smem_bytes = SMEM_FLOATS * (int)sizeof(float);   // 50688 B
    cudaFuncSetAttribute(ssk_diag_kernel,
                         cudaFuncAttributeMaxDynamicSharedMemorySize, smem_bytes);

    ssk_diag_kernel<<<HDIM, 128, smem_bytes>>>(log_dt, log_w_real, w_imag,
                                               C_re, C_im, out);
}

// round 5
// speedup vs baseline: 1.3941x; 1.0417x over previous
#include <cuda_runtime.h>

// S4D diagonal SSM: out[h,l] = 2*Re( sum_n cmod[h,n] * z[h,n]^l ),  z = exp(w*dt)
// Factor l = 64k + j (k in [0,32), j in [0,64)):
//   out[h,64k+j] = sum_n ( Bre[n,k]*Are[n,j] - Bim[n,k]*Aim[n,j] )
// Packing trick: A[n][j]=(ar,ai) float2, B[k][n]=(br,-bi) float2.
// fma.rn.f32x2 acc += B ⊗ A accumulates {Σ br*ar, Σ -bi*ai}; out = lo+hi.
// R5: fully unrolled n-loop -> immediate LDS offsets, no branch, ptxas pipelining.

#define HDIM 1024
#define NDIM 64
#define LLEN 2048

#define AST 66                       // A row stride in float2 (64 + 2 pad; 16B-aligned)
#define BST 66                       // B row stride in float2 (132 words: 4*kq bank quads)
#define A_FLOATS (64*AST*2)          // 8448 floats (33792 B)
#define B_FLOATS (32*BST*2)          // 4224 floats (16896 B)
#define SMEM_FLOATS (A_FLOATS + B_FLOATS)   // 12672 floats = 50688 B

struct c2 { float re, im; };
__device__ __forceinline__ c2 cmul(c2 a, c2 b) {
    return { fmaf(a.re, b.re, -a.im*b.im), fmaf(a.re, b.im, a.im*b.re) };
}

__device__ __forceinline__ void fma2(unsigned long long& d,
                                     unsigned long long a,
                                     unsigned long long b) {
    asm("fma.rn.f32x2 %0, %1, %2, %0;" : "+l"(d) : "l"(a), "l"(b));
}

union U2 { unsigned long long u; float2 f; };

__global__ __launch_bounds__(128, 4) void ssk_diag_kernel(
    const float* __restrict__ log_dt,
    const float* __restrict__ log_w_real,
    const float* __restrict__ w_imag,
    const float* __restrict__ C_re,
    const float* __restrict__ C_im,
    float* __restrict__ out)
{
    extern __shared__ float sm[];
    float2* sA = reinterpret_cast<float2*>(sm);              // [64 n][AST]
    float2* sB = reinterpret_cast<float2*>(sm + A_FLOATS);   // [32 k][BST]

    const int h   = blockIdx.x;
    const int tid = threadIdx.x;

    // ------------- Phase 1: tables. tid = half*64 + n (2 threads per n) -------------
    {
        const int n    = tid & 63;
        const int half = tid >> 6;

        const float dtv = expf(log_dt[h]);
        const float wre = -expf(log_w_real[h*NDIM + n]);
        const float wim = w_imag[h*NDIM + n];
        const float are = wre * dtv;
        const float aim = wim * dtv;

        const float er = expf(are);
        float s, c; sincosf(aim, &s, &c);
        const c2 z = { er*c, er*s };

        // cmod = 2 * C * (z - 1) / w  (fold output factor 2)
        const float nre = z.re - 1.0f, nim = z.im;
        const float inv = 1.0f / (wre*wre + wim*wim);
        const float tre = (nre*wre + nim*wim) * inv;
        const float tim = (nim*wre - nre*wim) * inv;
        const float cr = C_re[h*NDIM + n], ci = C_im[h*NDIM + n];
        const c2 cm = { 2.0f*(cr*tre - ci*tim), 2.0f*(cr*tim + ci*tre) };

        // power ladder by squaring
        const c2 z2    = cmul(z,    z);
        const c2 z4    = cmul(z2,   z2);
        const c2 z8    = cmul(z4,   z4);
        const c2 z16   = cmul(z8,   z8);
        const c2 z32   = cmul(z16,  z16);
        const c2 z64   = cmul(z32,  z32);
        const c2 z128  = cmul(z64,  z64);
        const c2 z256  = cmul(z128, z128);
        const c2 z512  = cmul(z256, z256);
        const c2 z1024 = cmul(z512, z512);

        // A[n][j] = (re,im) of z^j, j = 32*half .. 32*half+31
        c2 a = half ? z32 : c2{1.0f, 0.0f};
        #pragma unroll
        for (int jj = 0; jj < 32; jj++) {
            sA[n*AST + 32*half + jj] = make_float2(a.re, a.im);
            a = cmul(a, z);
        }

        // B[k][n] = (re, -im) of cmod * z64^k, k = 16*half .. 16*half+15
        c2 b = half ? cmul(cm, z1024) : cm;
        #pragma unroll
        for (int kk = 0; kk < 16; kk++) {
            sB[(16*half + kk)*BST + n] = make_float2(b.re, -b.im);
            b = cmul(b, z64);
        }
    }
    __syncthreads();

    // ------------- Phase 2: contraction. tid = jp*8 + kq ----------------------------
    // Thread tile: k = kq + 8*kk (kk 0..3), j = 4*jp + jj (jj 0..3). 16 outputs.
    const int jp = tid >> 3;    // 0..15
    const int kq = tid & 7;     // 0..7

    const char* pA = reinterpret_cast<const char*>(sA) + (size_t)jp * 32;
    const char* pB = reinterpret_cast<const char*>(sB) + (size_t)kq * (BST*8);

    unsigned long long acc[4][4];   // [kk][jj]
    #pragma unroll
    for (int i = 0; i < 4; i++)
        #pragma unroll
        for (int jj = 0; jj < 4; jj++) acc[i][jj] = 0ull;

    #define LDA(off) (*reinterpret_cast<const ulonglong2*>(pA + (off)))
    #define LDB(off) (*reinterpret_cast<const ulonglong2*>(pB + (off)))

    // Fully unrolled: every offset is a compile-time immediate -> zero address
    // IMADs, no branches; ptxas pipelines the LDS stream itself.
    #pragma unroll
    for (int n2 = 0; n2 < 32; n2++) {
        const int na = 2*n2, nb = 2*n2 + 1;
        const ulonglong2 a0 = LDA((size_t)na*AST*8);
        const ulonglong2 a1 = LDA((size_t)na*AST*8 + 16);
        const ulonglong2 a2 = LDA((size_t)nb*AST*8);
        const ulonglong2 a3 = LDA((size_t)nb*AST*8 + 16);
        const ulonglong2 b0 = LDB((size_t)na*8);
        const ulonglong2 b1 = LDB((size_t)BST*8*8  + na*8);
        const ulonglong2 b2 = LDB((size_t)BST*8*16 + na*8);
        const ulonglong2 b3 = LDB((size_t)BST*8*24 + na*8);

        // even n: b*.x ; odd n: b*.y
        fma2(acc[0][0], b0.x, a0.x);  fma2(acc[0][1], b0.x, a0.y);
        fma2(acc[0][2], b0.x, a1.x);  fma2(acc[0][3], b0.x, a1.y);
        fma2(acc[1][0], b1.x, a0.x);  fma2(acc[1][1], b1.x, a0.y);
        fma2(acc[1][2], b1.x, a1.x);  fma2(acc[1][3], b1.x, a1.y);
        fma2(acc[2][0], b2.x, a0.x);  fma2(acc[2][1], b2.x, a0.y);
        fma2(acc[2][2], b2.x, a1.x);  fma2(acc[2][3], b2.x, a1.y);
        fma2(acc[3][0], b3.x, a0.x);  fma2(acc[3][1], b3.x, a0.y);
        fma2(acc[3][2], b3.x, a1.x);  fma2(acc[3][3], b3.x, a1.y);

        fma2(acc[0][0], b0.y, a2.x);  fma2(acc[0][1], b0.y, a2.y);
        fma2(acc[0][2], b0.y, a3.x);  fma2(acc[0][3], b0.y, a3.y);
        fma2(acc[1][0], b1.y, a2.x);  fma2(acc[1][1], b1.y, a2.y);
        fma2(acc[1][2], b1.y, a3.x);  fma2(acc[1][3], b1.y, a3.y);
        fma2(acc[2][0], b2.y, a2.x);  fma2(acc[2][1], b2.y, a2.y);
        fma2(acc[2][2], b2.y, a3.x);  fma2(acc[2][3], b2.y, a3.y);
        fma2(acc[3][0], b3.y, a2.x);  fma2(acc[3][1], b3.y, a2.y);
        fma2(acc[3][2], b3.y, a3.x);  fma2(acc[3][3], b3.y, a3.y);
    }
    #undef LDA
    #undef LDB

    // Reduce packed halves and store: l = 64*(kq+8*kk) + 4*jp + jj
    float* po = out + h*LLEN + kq*64 + jp*4;
    #pragma unroll
    for (int kk = 0; kk < 4; kk++) {
        float4 v;
        { U2 u; u.u = acc[kk][0]; v.x = u.f.x + u.f.y; }
        { U2 u; u.u = acc[kk][1]; v.y = u.f.x + u.f.y; }
        { U2 u; u.u = acc[kk][2]; v.z = u.f.x + u.f.y; }
        { U2 u; u.u = acc[kk][3]; v.w = u.f.x + u.f.y; }
        *reinterpret_cast<float4*>(po + kk*512) = v;
    }
}

extern "C" void kernel_launch(void* const* d_in, const int* in_sizes, int n_in,
                              void* d_out, int out_size)
{
    const float* log_dt     = (const float*)d_in[0];
    const float* log_w_real = (const float*)d_in[1];
    const float* w_imag     = (const float*)d_in[2];
    const float* C_re       = (const float*)d_in[3];
    const float* C_im       = (const float*)d_in[4];
    float* out = (float*)d_out;

    const int smem_bytes = SMEM_FLOATS * (int)sizeof(float);   // 50688 B
    cudaFuncSetAttribute(ssk_diag_kernel,
                         cudaFuncAttributeMaxDynamicSharedMemorySize, smem_bytes);

    ssk_diag_kernel<<<HDIM, 128, smem_bytes>>>(log_dt, log_w_real, w_imag,
                                               C_re, C_im, out);
}